// round 15
// baseline (speedup 1.0000x reference)
#include <cuda_runtime.h>
#include <cuda_bf16.h>
#include <math.h>

#define BATCH 4
#define HW    30976            // 176*176
#define PTOT  123904           // BATCH*HW
#define NWIN  1936             // 44*44
#define PB    3964928ULL       // per-batch plane = 128*30976

// uint-unit offsets into the single scratch buffer
#define OFF_AQ    0ULL          // tiled bf16x2, K=128 (8 stages/blk)
#define OFF_AKV   7929856ULL    // tiled bf16x2, K=128
#define OFF_Q     31719424ULL   // packed bf16x2 [p][64]
#define OFF_KV    47579136ULL   // packed bf16x2 [p][128] (K | V)
#define OFF_X1    79298560ULL   // fp32 NCHW residual (written by k_attn)
#define OFF_X1LN  95158272ULL   // tiled bf16x2, K=128
#define OFF_YIN   103088128ULL  // packed bf16x2 [p][512]
#define OFF_YG    166526976ULL  // packed bf16x2 [p][256]
#define OFF_WB    198246400ULL
#define TOT_U     198369280ULL

__device__ unsigned g_u[TOT_U];

// ---------------------------------------------------------------------------
// helpers
// ---------------------------------------------------------------------------
__device__ __forceinline__ unsigned pk(float lo, float hi) {
    unsigned r;
    asm("cvt.rn.bf16x2.f32 %0, %1, %2;" : "=r"(r) : "f"(hi), "f"(lo));
    return r;
}
__device__ __forceinline__ float2 bf2f(unsigned u) {
    __nv_bfloat162 h = *reinterpret_cast<__nv_bfloat162*>(&u);
    return __bfloat1622float2(h);
}
__device__ __forceinline__ void mma16(float* d, const unsigned* a, const unsigned* b) {
    asm volatile(
        "mma.sync.aligned.m16n8k16.row.col.f32.bf16.bf16.f32 "
        "{%0,%1,%2,%3},{%4,%5,%6,%7},{%8,%9},{%0,%1,%2,%3};"
        : "+f"(d[0]), "+f"(d[1]), "+f"(d[2]), "+f"(d[3])
        : "r"(a[0]), "r"(a[1]), "r"(a[2]), "r"(a[3]), "r"(b[0]), "r"(b[1]));
}
__device__ __forceinline__ void ldsm4(unsigned& r0, unsigned& r1, unsigned& r2, unsigned& r3, unsigned a) {
    asm volatile("ldmatrix.sync.aligned.m8n8.x4.shared.b16 {%0,%1,%2,%3}, [%4];"
        : "=r"(r0), "=r"(r1), "=r"(r2), "=r"(r3) : "r"(a));
}
__device__ __forceinline__ void cpa16(unsigned d, const void* s) {
    asm volatile("cp.async.cg.shared.global [%0], [%1], 16;" :: "r"(d), "l"(s));
}
__device__ __forceinline__ void stg_cs(unsigned* p, unsigned v) {
    asm volatile("st.global.cs.u32 [%0], %1;" :: "l"(p), "r"(v));
}
__device__ __forceinline__ void stg_cs_f(float* p, float v) {
    asm volatile("st.global.cs.f32 [%0], %1;" :: "l"(p), "f"(v));
}
#define CP_COMMIT() asm volatile("cp.async.commit_group;" ::: "memory")
#define CP_WAIT2()  asm volatile("cp.async.wait_group 2;" ::: "memory")
#define CP_WAIT1()  asm volatile("cp.async.wait_group 1;" ::: "memory")
#define CP_WAIT0()  asm volatile("cp.async.wait_group 0;" ::: "memory")

// packed f32x2 helpers (sm_100-family PTX, not arch-accelerated)
__device__ __forceinline__ unsigned long long u2f2(unsigned u) {
    unsigned lo = u << 16, hi = u & 0xFFFF0000u;
    unsigned long long r;
    asm("mov.b64 %0, {%1,%2};" : "=l"(r) : "r"(lo), "r"(hi));
    return r;
}
__device__ __forceinline__ unsigned long long pkf2(float lo, float hi) {
    unsigned long long r;
    asm("mov.b64 %0, {%1,%2};" : "=l"(r) : "f"(lo), "f"(hi));
    return r;
}
__device__ __forceinline__ unsigned long long ffma2(
    unsigned long long a, unsigned long long b, unsigned long long c) {
    unsigned long long d;
    asm("fma.rn.f32x2 %0, %1, %2, %3;" : "=l"(d) : "l"(a), "l"(b), "l"(c));
    return d;
}
__device__ __forceinline__ void unf2(unsigned long long v, float& lo, float& hi) {
    asm("mov.b64 {%0,%1}, %2;" : "=f"(lo), "=f"(hi) : "l"(v));
}

// ---------------------------------------------------------------------------
// K0: weight prep -> packed bf16x2 in GEMM-tiled layout.
// WB: WqP[8192] | WKVP[16384] | WinP[65536] | WoutP[32768]
// ---------------------------------------------------------------------------
__global__ void k_wprep(const float* __restrict__ Wq, const float* __restrict__ Wk,
                        const float* __restrict__ Wv, const float* __restrict__ win,
                        const float* __restrict__ wout)
{
    int idx = blockIdx.x * 256 + threadIdx.x;
    if (idx >= 122880) return;
    unsigned* WB = g_u + OFF_WB;
    if (idx < 8192) {
        int n = idx >> 6, kp = idx & 63;
        WB[(kp >> 3) * 1024 + n * 8 + (kp & 7)] = pk(Wq[n * 128 + 2 * kp], Wq[n * 128 + 2 * kp + 1]);
    } else if (idx < 24576) {
        int j = idx - 8192; int n2 = j >> 6, kp = j & 63;
        const float* W = (n2 < 128) ? Wk : Wv;
        int n = n2 & 127;
        WB[8192 + (n2 >> 7) * 8192 + (kp >> 3) * 1024 + n * 8 + (kp & 7)]
            = pk(W[n * 128 + 2 * kp], W[n * 128 + 2 * kp + 1]);
    } else if (idx < 90112) {
        int j = idx - 24576; int n = j >> 6, kp = j & 63;
        WB[24576 + (n >> 7) * 8192 + (kp >> 3) * 1024 + (n & 127) * 8 + (kp & 7)]
            = pk(win[n * 128 + 2 * kp], win[n * 128 + 2 * kp + 1]);
    } else {
        int j = idx - 90112; int n = j >> 8, kp = j & 255;
        WB[90112 + (kp >> 3) * 1024 + n * 8 + (kp & 7)]
            = pk(wout[n * 512 + 2 * kp], wout[n * 512 + 2 * kp + 1]);
    }
}

// ---------------------------------------------------------------------------
// K1: LN1(x), bilinear mask/edge upsample -> tiled Aq / Akv (uint4 stores).
// ---------------------------------------------------------------------------
__global__ void __launch_bounds__(256) k_prep(
    const float* __restrict__ x, const float* __restrict__ mask,
    const float* __restrict__ edge, const float* __restrict__ ln1w,
    const float* __restrict__ ln1b)
{
    __shared__ float xs[128 * 33];
    __shared__ float red[264], red2[264];
    __shared__ float ms[32], mu_s[32], rs_s[32];
    __shared__ int   cy0[32], cy1[32], cx0[32], cx1[32];
    __shared__ float cwy[32], cwx[32];
    __shared__ float w1s[128], b1s[128];

    int p0 = blockIdx.x * 32;
    int b = p0 / HW, hw0 = p0 % HW;
    const float* xb = x + (size_t)b * PB;
    if (threadIdx.x < 128) { w1s[threadIdx.x] = ln1w[threadIdx.x]; b1s[threadIdx.x] = ln1b[threadIdx.x]; }

    for (int e = threadIdx.x; e < 4096; e += 256) {
        int c = e >> 5, px = e & 31;
        xs[c * 33 + px] = xb[(size_t)c * HW + hw0 + px];
    }
    if (threadIdx.x < 32) {
        int px = threadIdx.x;
        int hw = hw0 + px;
        int h2 = hw / 176, w2 = hw % 176;
        float fy = 0.25f * h2 - 0.375f; int iy = (int)floorf(fy); float ty = fy - iy;
        float fx = 0.25f * w2 - 0.375f; int ix = (int)floorf(fx); float tx = fx - ix;
        int y0 = iy < 0 ? 0 : iy, y1 = (iy + 1 > 43) ? 43 : iy + 1;
        int x0 = ix < 0 ? 0 : ix, x1 = (ix + 1 > 43) ? 43 : ix + 1;
        cy0[px] = y0; cy1[px] = y1; cx0[px] = x0; cx1[px] = x1;
        cwy[px] = ty; cwx[px] = tx;
        const float* mb = mask + b * NWIN;
        ms[px] = (1.f - ty) * ((1.f - tx) * mb[y0 * 44 + x0] + tx * mb[y0 * 44 + x1])
               +        ty  * ((1.f - tx) * mb[y1 * 44 + x0] + tx * mb[y1 * 44 + x1]);
    }
    __syncthreads();
    {
        int px = threadIdx.x & 31, j = threadIdx.x >> 5;
        float s = 0.f, s2 = 0.f;
        #pragma unroll
        for (int i = 0; i < 16; i++) {
            float v = xs[(j * 16 + i) * 33 + px];
            s += v; s2 += v * v;
        }
        red[j * 33 + px] = s; red2[j * 33 + px] = s2;
    }
    __syncthreads();
    if (threadIdx.x < 32) {
        int px = threadIdx.x; float s = 0.f, s2 = 0.f;
        #pragma unroll
        for (int j = 0; j < 8; j++) { s += red[j * 33 + px]; s2 += red2[j * 33 + px]; }
        float mu = s * (1.f / 128.f);
        float var = s2 * (1.f / 128.f) - mu * mu;
        mu_s[px] = mu; rs_s[px] = rsqrtf(var + 1e-5f);
    }
    __syncthreads();

    int px = threadIdx.x & 31, j = threadIdx.x >> 5;   // j = stage 0..7
    int p = p0 + px;
    size_t tbase = (size_t)(p >> 7) * 8192 + (size_t)j * 1024 + (size_t)(p & 127) * 8;
    {
        float mu = mu_s[px], rs = rs_s[px], m = ms[px];
        unsigned q[8];
        #pragma unroll
        for (int ii = 0; ii < 8; ii++) {
            int c = j * 16 + 2 * ii;
            float v0 = ((xs[c * 33 + px] - mu) * rs * w1s[c] + b1s[c]) * m;
            float v1 = ((xs[(c + 1) * 33 + px] - mu) * rs * w1s[c + 1] + b1s[c + 1]) * m;
            q[ii] = pk(v0, v1);
        }
        uint4* dst = (uint4*)(g_u + OFF_AKV + tbase);
        dst[0] = make_uint4(q[0], q[1], q[2], q[3]);
        dst[1] = make_uint4(q[4], q[5], q[6], q[7]);
    }
    __syncthreads();
    for (int e = threadIdx.x; e < 4096; e += 256) {
        int c = e >> 5, px2 = e & 31;
        const float* eb = edge + ((size_t)b * 128 + c) * NWIN;
        float ty = cwy[px2], tx = cwx[px2];
        float v = (1.f - ty) * ((1.f - tx) * eb[cy0[px2] * 44 + cx0[px2]] + tx * eb[cy0[px2] * 44 + cx1[px2]])
                +        ty  * ((1.f - tx) * eb[cy1[px2] * 44 + cx0[px2]] + tx * eb[cy1[px2] * 44 + cx1[px2]]);
        xs[c * 33 + px2] = v;
    }
    __syncthreads();
    {
        unsigned q[8];
        #pragma unroll
        for (int ii = 0; ii < 8; ii++) {
            int c = j * 16 + 2 * ii;
            q[ii] = pk(xs[c * 33 + px], xs[(c + 1) * 33 + px]);
        }
        uint4* dst = (uint4*)(g_u + OFF_AQ + tbase);
        dst[0] = make_uint4(q[0], q[1], q[2], q[3]);
        dst[1] = make_uint4(q[4], q[5], q[6], q[7]);
    }
}

// ---------------------------------------------------------------------------
// Shared GEMM mainloop pieces (R10-proven: 4-buffer, 3 in flight, 1 bar/stage)
// ---------------------------------------------------------------------------
#define GEMM_PREAMBLE() \
    int tid = threadIdx.x, lane = tid & 31, warp = tid >> 5; \
    int wm = warp >> 2, wn = warp & 3, t = lane & 3, g = lane >> 2; \
    unsigned smb = (unsigned)__cvta_generic_to_shared(sm); \
    int m_ = tid >> 1, q_ = tid & 1; \
    unsigned dA = smb + (unsigned)(2 * m_ + (q_ ^ ((m_ >> 2) & 1))) * 16; \
    unsigned dB = dA + 4096; \
    int itemA = wm * 64 + (lane & 15); \
    int khA = lane >> 4; \
    unsigned aAddr = smb + (unsigned)(2 * itemA + (khA ^ ((itemA >> 2) & 1))) * 16; \
    int itemB = wn * 32 + lane; \
    int bbit = (itemB >> 2) & 1; \
    unsigned bAddr0 = smb + 4096u + (unsigned)(2 * itemB + bbit) * 16; \
    unsigned bAddr1 = smb + 4096u + (unsigned)(2 * itemB + (1 ^ bbit)) * 16; \
    float acc[4][4][4]; \
    _Pragma("unroll") \
    for (int i = 0; i < 4; i++) \
        _Pragma("unroll") \
        for (int j = 0; j < 4; j++) \
            _Pragma("unroll") \
            for (int k = 0; k < 4; k++) acc[i][j][k] = 0.f;

#define GEMM_STAGE_BODY() \
    unsigned buf = (unsigned)(s & 3) * 8192u; \
    unsigned af[4][4], bf[4][2]; \
    ldsm4(bf[0][0], bf[1][0], bf[2][0], bf[3][0], bAddr0 + buf); \
    ldsm4(bf[0][1], bf[1][1], bf[2][1], bf[3][1], bAddr1 + buf); \
    _Pragma("unroll") \
    for (int tm = 0; tm < 4; tm++) \
        ldsm4(af[tm][0], af[tm][1], af[tm][2], af[tm][3], aAddr + buf + tm * 512u); \
    _Pragma("unroll") \
    for (int tm = 0; tm < 4; tm++) \
        _Pragma("unroll") \
        for (int tn = 0; tn < 4; tn++) \
            mma16(acc[tm][tn], af[tm], bf[tn]);

// ---------------------------------------------------------------------------
// K2a: fused Q/K/V GEMM. grid (PTOT/128, 3). y=0->Q, y=1->K half, y=2->V half.
// ---------------------------------------------------------------------------
__global__ void __launch_bounds__(256, 2) k_mma_qkv()
{
    __shared__ unsigned sm[4 * 2048];
    GEMM_PREAMBLE();
    int y = blockIdx.y;
    const unsigned* Ab = g_u + (y == 0 ? OFF_AQ : OFF_AKV)
                       + (size_t)blockIdx.x * 8192 + tid * 4;
    const unsigned* Bb = g_u + OFF_WB + (size_t)y * 8192 + tid * 4;

    #pragma unroll
    for (int s = 0; s < 3; s++) {
        unsigned off = s * 8192u;
        cpa16(dA + off, Ab + s * 1024);
        cpa16(dB + off, Bb + s * 1024);
        CP_COMMIT();
    }
    for (int s = 0; s < 8; s++) {
        if (s + 3 <= 8) CP_WAIT2();
        else if (s + 2 == 8) CP_WAIT1();
        else CP_WAIT0();
        __syncthreads();
        GEMM_STAGE_BODY();
        if (s + 3 < 8) {
            unsigned off = (unsigned)((s + 3) & 3) * 8192u;
            cpa16(dA + off, Ab + (s + 3) * 1024);
            cpa16(dB + off, Bb + (s + 3) * 1024);
        }
        CP_COMMIT();
    }

    int m0 = blockIdx.x * 128;
    unsigned* Cu = g_u + (y == 0 ? OFF_Q : OFF_KV);
    int np = (y == 0) ? 64 : 128;
    int nc0 = (y == 0) ? 0 : (y - 1) * 64;
    #pragma unroll
    for (int tm = 0; tm < 4; tm++)
        #pragma unroll
        for (int tn = 0; tn < 4; tn++) {
            int m = m0 + wm * 64 + tm * 16 + g;
            int n = wn * 32 + tn * 8 + 2 * t;
            Cu[(size_t)m * np + nc0 + (n >> 1)] = pk(acc[tm][tn][0], acc[tm][tn][1]);
            Cu[(size_t)(m + 8) * np + nc0 + (n >> 1)] = pk(acc[tm][tn][2], acc[tm][tn][3]);
        }
}

// ---------------------------------------------------------------------------
// K2b: generic GEMM (conv_in EPI=1/CS, conv_out EPI=2) — R10-proven.
// ---------------------------------------------------------------------------
template<int NSTAGE, int ASRC, int EPI, int CS>
__global__ void __launch_bounds__(256, 2) k_mma_t(
    const unsigned* __restrict__ At, const unsigned* __restrict__ Bt,
    unsigned* __restrict__ Cu, int Nd, float* __restrict__ outp)
{
    __shared__ unsigned sm[4 * 2048];
    GEMM_PREAMBLE();
    const unsigned* Ab;
    if (ASRC == 0) Ab = At + (size_t)blockIdx.x * (NSTAGE * 1024) + tid * 4;
    else           Ab = At + ((size_t)blockIdx.x * 128 + (tid >> 1)) * 256 + (tid & 1) * 4;
    const unsigned* Bb = Bt + (size_t)blockIdx.y * (NSTAGE * 1024) + tid * 4;

    #pragma unroll
    for (int s = 0; s < 3; s++) {
        if (s < NSTAGE) {
            unsigned off = s * 8192u;
            cpa16(dA + off, Ab + (ASRC == 0 ? s * 1024 : s * 8));
            cpa16(dB + off, Bb + s * 1024);
        }
        CP_COMMIT();
    }
    for (int s = 0; s < NSTAGE; s++) {
        if (s + 3 <= NSTAGE) CP_WAIT2();
        else if (s + 2 == NSTAGE) CP_WAIT1();
        else CP_WAIT0();
        __syncthreads();
        GEMM_STAGE_BODY();
        if (s + 3 < NSTAGE) {
            unsigned off = (unsigned)((s + 3) & 3) * 8192u;
            cpa16(dA + off, Ab + (ASRC == 0 ? (s + 3) * 1024 : (s + 3) * 8));
            cpa16(dB + off, Bb + (s + 3) * 1024);
        }
        CP_COMMIT();
    }

    int m0 = blockIdx.x * 128, n0 = blockIdx.y * 128;
    if (EPI == 1) {
        int np = Nd >> 1;
        #pragma unroll
        for (int tm = 0; tm < 4; tm++)
            #pragma unroll
            for (int tn = 0; tn < 4; tn++) {
                int m = m0 + wm * 64 + tm * 16 + g;
                int n = n0 + wn * 32 + tn * 8 + 2 * t;
                unsigned v0 = pk(acc[tm][tn][0], acc[tm][tn][1]);
                unsigned v1 = pk(acc[tm][tn][2], acc[tm][tn][3]);
                if (CS) {
                    stg_cs(Cu + (size_t)m * np + (n >> 1), v0);
                    stg_cs(Cu + (size_t)(m + 8) * np + (n >> 1), v1);
                } else {
                    Cu[(size_t)m * np + (n >> 1)] = v0;
                    Cu[(size_t)(m + 8) * np + (n >> 1)] = v1;
                }
            }
    } else {
        const float* x1 = (const float*)(g_u + OFF_X1);
        int b = m0 / HW, hw0 = m0 % HW;
        #pragma unroll
        for (int tm = 0; tm < 4; tm++)
            #pragma unroll
            for (int tn = 0; tn < 4; tn++) {
                int mrow = wm * 64 + tm * 16 + g;
                int n = wn * 32 + tn * 8 + 2 * t;
                size_t a0 = ((size_t)b * 128 + n) * HW + hw0 + mrow;
                stg_cs_f(outp + a0,          x1[a0] + acc[tm][tn][0]);
                stg_cs_f(outp + a0 + HW,     x1[a0 + HW] + acc[tm][tn][1]);
                stg_cs_f(outp + a0 + 8,      x1[a0 + 8] + acc[tm][tn][2]);
                stg_cs_f(outp + a0 + HW + 8, x1[a0 + HW + 8] + acc[tm][tn][3]);
            }
    }
}

// ---------------------------------------------------------------------------
// K3: channel attention + fused residual (R13-proven), uint4 Q/KV loads.
// ds stored TRANSPOSED with stride 17: ds[kk*17 + j].
// ---------------------------------------------------------------------------
__global__ void __launch_bounds__(256) k_attn(const float* __restrict__ x)
{
    __shared__ float outs[32 * 129];
    __shared__ float buf[8 * 656];
    int bid = blockIdx.x;
    int chunk = bid % 61;
    int n = (bid / 61) % 16;
    int b = bid / (61 * 16);
    int ihw0 = chunk * 32;
    const unsigned* Qp  = g_u + OFF_Q;
    const unsigned* KVp = g_u + OFF_KV;
    float* x1 = (float*)(g_u + OFF_X1);
    int warp = threadIdx.x >> 5, lane = threadIdx.x & 31;
    float* qs = buf + warp * 656;
    float* ks = qs + 128;
    float* vs = qs + 256;
    float* ds = qs + 384;          // 16x16 stored transposed, stride 17
    int kk = lane & 15, hh = lane >> 4;

    for (int it = 0; it < 4; it++) {
        int g = it * 8 + warp;
        int ihw = ihw0 + g;
        if (ihw < NWIN) {
            int ih = ihw / 44, iw = ihw % 44;
            int h2 = ih * 4 + (n >> 2), w2 = iw * 4 + (n & 3);
            size_t p = (size_t)b * HW + (size_t)h2 * 176 + w2;
            {
                // Q: 16 uint4 (lanes 0..15), KV: 32 uint4 (K: lanes<16, V: lanes>=16)
                if (lane < 16) {
                    uint4 qv4 = *(const uint4*)(Qp + p * 64 + lane * 4);
                    float* dq = qs + lane * 8;
                    *(float2*)(dq)     = bf2f(qv4.x);
                    *(float2*)(dq + 2) = bf2f(qv4.y);
                    *(float2*)(dq + 4) = bf2f(qv4.z);
                    *(float2*)(dq + 6) = bf2f(qv4.w);
                }
                uint4 kv4 = *(const uint4*)(KVp + p * 128 + lane * 4);
                float* dkv = (lane < 16) ? (ks + lane * 8) : (vs + (lane - 16) * 8);
                *(float2*)(dkv)     = bf2f(kv4.x);
                *(float2*)(dkv + 2) = bf2f(kv4.y);
                *(float2*)(dkv + 4) = bf2f(kv4.z);
                *(float2*)(dkv + 6) = bf2f(kv4.w);
            }
            __syncwarp();
            {
                float kreg[8];
                #pragma unroll
                for (int i = 0; i < 8; i++) kreg[i] = ks[i * 16 + kk];
                #pragma unroll
                for (int t2 = 0; t2 < 8; t2++) {
                    int j = hh + 2 * t2;
                    float s = 0.f;
                    #pragma unroll
                    for (int i = 0; i < 8; i++) s += qs[i * 16 + j] * kreg[i];
                    ds[kk * 17 + j] = s * 0.25f;
                }
            }
            __syncwarp();
            if (lane < 16) {
                float mx = -1e30f;
                #pragma unroll
                for (int k2 = 0; k2 < 16; k2++) mx = fmaxf(mx, ds[k2 * 17 + lane]);
                float sm = 0.f;
                #pragma unroll
                for (int k2 = 0; k2 < 16; k2++) {
                    float ev = __expf(ds[k2 * 17 + lane] - mx);
                    ds[k2 * 17 + lane] = ev; sm += ev;
                }
                float inv = 1.f / sm;
                #pragma unroll
                for (int k2 = 0; k2 < 16; k2++) ds[k2 * 17 + lane] *= inv;
            }
            __syncwarp();
            {
                float dreg[16];
                #pragma unroll
                for (int k2 = 0; k2 < 16; k2++) dreg[k2] = ds[k2 * 17 + kk];
                #pragma unroll
                for (int t2 = 0; t2 < 4; t2++) {
                    int i = hh + 2 * t2;
                    float s = 0.f;
                    #pragma unroll
                    for (int k2 = 0; k2 < 16; k2++) s += dreg[k2] * vs[i * 16 + k2];
                    outs[g * 129 + i * 16 + kk] = s;
                }
            }
        }
    }
    __syncthreads();
    size_t base = ((size_t)b * 2048 + (size_t)n * 128) * 1936 + ihw0;
    for (int e = threadIdx.x; e < 4096; e += 256) {
        int ch = e >> 5, g = e & 31;
        if (ihw0 + g < NWIN) {
            size_t idx = base + (size_t)ch * 1936 + g;
            x1[idx] = x[idx] + outs[g * 129 + ch];
        }
    }
}

// ---------------------------------------------------------------------------
// K4: LN2 over x1 (read-only) -> tiled X1LN packed bf16 (uint4 stores).
// ---------------------------------------------------------------------------
__global__ void __launch_bounds__(256) k_merge2(
    const float* __restrict__ ln2w, const float* __restrict__ ln2b)
{
    __shared__ float red[264], red2[264], mu_s[32], rs_s[32];
    __shared__ float w2s[128], b2s[128];
    int p0 = blockIdx.x * 32;
    int b = p0 / HW, hw0 = p0 % HW;
    int px = threadIdx.x & 31, j = threadIdx.x >> 5;
    if (threadIdx.x < 128) { w2s[threadIdx.x] = ln2w[threadIdx.x]; b2s[threadIdx.x] = ln2b[threadIdx.x]; }
    const float* x1 = (const float*)(g_u + OFF_X1);
    size_t base = (size_t)b * PB + hw0 + px;
    float v[16];
    float s = 0.f, s2 = 0.f;
    #pragma unroll
    for (int i = 0; i < 16; i++) {
        int c = j * 16 + i;
        float val = x1[base + (size_t)c * HW];
        v[i] = val; s += val; s2 += val * val;
    }
    red[j * 33 + px] = s; red2[j * 33 + px] = s2;
    __syncthreads();
    if (threadIdx.x < 32) {
        float ss = 0.f, ss2 = 0.f;
        #pragma unroll
        for (int j2 = 0; j2 < 8; j2++) { ss += red[j2 * 33 + threadIdx.x]; ss2 += red2[j2 * 33 + threadIdx.x]; }
        float mu = ss * (1.f / 128.f);
        float var = ss2 * (1.f / 128.f) - mu * mu;
        mu_s[threadIdx.x] = mu; rs_s[threadIdx.x] = rsqrtf(var + 1e-5f);
    }
    __syncthreads();
    float mu = mu_s[px], rs = rs_s[px];
    int p = p0 + px;
    unsigned qv[8];
    #pragma unroll
    for (int ii = 0; ii < 8; ii++) {
        int c = j * 16 + 2 * ii;
        float a = (v[2 * ii] - mu) * rs * w2s[c] + b2s[c];
        float bb = (v[2 * ii + 1] - mu) * rs * w2s[c + 1] + b2s[c + 1];
        qv[ii] = pk(a, bb);
    }
    uint4* dst = (uint4*)(g_u + OFF_X1LN + (size_t)(p >> 7) * 8192 + (size_t)j * 1024 + (size_t)(p & 127) * 8);
    dst[0] = make_uint4(qv[0], qv[1], qv[2], qv[3]);
    dst[1] = make_uint4(qv[4], qv[5], qv[6], qv[7]);
}

// ---------------------------------------------------------------------------
// K6: depthwise 3x3 + exact GELU gate, packed f32x2 accumulation.
// ---------------------------------------------------------------------------
__device__ __forceinline__ void dw_row6(
    const unsigned* __restrict__ yin, int b, int h, int w0, int cp,
    unsigned* U, unsigned* V)
{
    #pragma unroll
    for (int dw = 0; dw < 6; dw++) { U[dw] = 0u; V[dw] = 0u; }
    if (h < 0 || h >= 176) return;
    #pragma unroll
    for (int dw = 0; dw < 6; dw++) {
        int ww = w0 - 1 + dw;
        if (ww < 0 || ww >= 176) continue;
        size_t base = ((size_t)b * HW + (size_t)h * 176 + ww) * 512;
        U[dw] = yin[base + cp];
        V[dw] = yin[base + 256 + cp];
    }
}

__global__ void __launch_bounds__(256) k_dwconv(const float* __restrict__ wdw)
{
    int cp = threadIdx.x;
    int blk = blockIdx.x;
    int wg = blk % 44;
    int hs = (blk / 44) % 8;
    int b  = blk / (44 * 8);
    int w0 = wg * 4;
    int h0 = hs * 22;
    const unsigned* yin = g_u + OFF_YIN;
    unsigned* yg = g_u + OFF_YG;
    int c0 = 2 * cp;
    unsigned long long wpA[9], wpB[9];
    #pragma unroll
    for (int t = 0; t < 9; t++) {
        wpA[t] = pkf2(__ldg(&wdw[c0 * 9 + t]), __ldg(&wdw[(c0 + 1) * 9 + t]));
        wpB[t] = pkf2(__ldg(&wdw[(512 + c0) * 9 + t]), __ldg(&wdw[(513 + c0) * 9 + t]));
    }
    unsigned U[3][6], V[3][6];
    dw_row6(yin, b, h0 - 1, w0, cp, U[0], V[0]);
    dw_row6(yin, b, h0,     w0, cp, U[1], V[1]);
    dw_row6(yin, b, h0 + 1, w0, cp, U[2], V[2]);

    for (int h = h0; h < h0 + 22; h++) {
        unsigned long long accA[4], accB[4];
        #pragma unroll
        for (int o = 0; o < 4; o++) { accA[o] = 0ULL; accB[o] = 0ULL; }
        #pragma unroll
        for (int dw = 0; dw < 6; dw++) {
            #pragma unroll
            for (int rr = 0; rr < 3; rr++) {
                unsigned long long ua = u2f2(U[rr][dw]);
                unsigned long long vb = u2f2(V[rr][dw]);
                #pragma unroll
                for (int o = 0; o < 4; o++) {
                    int cc = dw - o;
                    if (cc >= 0 && cc < 3) {
                        int tt = rr * 3 + cc;
                        accA[o] = ffma2(ua, wpA[tt], accA[o]);
                        accB[o] = ffma2(vb, wpB[tt], accB[o]);
                    }
                }
            }
        }
        #pragma unroll
        for (int o = 0; o < 4; o++) {
            float a0, a1, g0, g1;
            unf2(accA[o], a0, a1);
            unf2(accB[o], g0, g1);
            float e0 = 0.5f * a0 * (1.f + erff(a0 * 0.70710678118654752f));
            float e1 = 0.5f * a1 * (1.f + erff(a1 * 0.70710678118654752f));
            int p = b * HW + h * 176 + w0 + o;
            stg_cs(yg + (size_t)p * 256 + cp, pk(e0 * g0, e1 * g1));
        }
        #pragma unroll
        for (int dw = 0; dw < 6; dw++) {
            U[0][dw] = U[1][dw]; U[1][dw] = U[2][dw];
            V[0][dw] = V[1][dw]; V[1][dw] = V[2][dw];
        }
        dw_row6(yin, b, h + 2, w0, cp, U[2], V[2]);
    }
}

// ---------------------------------------------------------------------------
extern "C" void kernel_launch(void* const* d_in, const int* in_sizes, int n_in,
                              void* d_out, int out_size)
{
    const float* x    = (const float*)d_in[0];
    const float* mask = (const float*)d_in[1];
    const float* edge = (const float*)d_in[2];
    const float* ln1w = (const float*)d_in[3];
    const float* ln1b = (const float*)d_in[4];
    const float* Wq   = (const float*)d_in[5];
    const float* Wk   = (const float*)d_in[6];
    const float* Wv   = (const float*)d_in[7];
    const float* ln2w = (const float*)d_in[8];
    const float* ln2b = (const float*)d_in[9];
    const float* w_in = (const float*)d_in[10];
    const float* w_dw = (const float*)d_in[11];
    const float* w_out= (const float*)d_in[12];
    float* outp = (float*)d_out;

    unsigned* G = nullptr;
    cudaGetSymbolAddress((void**)&G, g_u);

    // K0: weights -> tiled packed bf16x2
    k_wprep<<<(122880 + 255) / 256, 256>>>(Wq, Wk, Wv, w_in, w_out);

    // K1: LN1 + resize -> tiled Aq/Akv
    k_prep<<<PTOT / 32, 256>>>(x, mask, edge, ln1w, ln1b);

    // K2a: fused Q/K/V GEMM (one launch, grid.y = 3)
    k_mma_qkv<<<dim3(PTOT / 128, 3), 256>>>();

    // K3: channel attention + fused residual -> x1 (fp32 NCHW)
    k_attn<<<4 * 16 * 61, 256>>>(x);

    // K4: LN2(x1) -> tiled X1LN
    k_merge2<<<PTOT / 32, 256>>>(ln2w, ln2b);

    // K5: conv1x1 128->1024 -> y_in packed bf16 (evict-first C stores)
    k_mma_t<8, 0, 1, 1><<<dim3(PTOT / 128, 8), 256>>>(G + OFF_X1LN, G + OFF_WB + 24576, G + OFF_YIN, 1024, nullptr);

    // K6: depthwise 3x3 + GELU gate -> y_g packed rows (f32x2 math, cs stores)
    k_dwconv<<<BATCH * 44 * 8, 256>>>(w_dw);

    // K7: conv1x1 512->128 + residual -> d_out (NCHW, cs stores)
    k_mma_t<32, 1, 2, 0><<<dim3(PTOT / 128, 1), 256>>>(G + OFF_YG, G + OFF_WB + 90112, nullptr, 128, outp);
}

// round 16
// speedup vs baseline: 1.0395x; 1.0395x over previous
#include <cuda_runtime.h>
#include <cuda_bf16.h>
#include <math.h>

#define BATCH 4
#define HW    30976            // 176*176
#define PTOT  123904           // BATCH*HW
#define NWIN  1936             // 44*44
#define PB    3964928ULL       // per-batch plane = 128*30976

// uint-unit offsets into the single scratch buffer
#define OFF_AQ    0ULL          // tiled bf16x2, K=128 (8 stages/blk)
#define OFF_AKV   7929856ULL    // tiled bf16x2, K=128
#define OFF_Q     31719424ULL   // packed bf16x2 [p][64]
#define OFF_KV    47579136ULL   // packed bf16x2 [p][128] (K | V)
#define OFF_X1    79298560ULL   // fp32 NCHW residual (written by k_attn)
#define OFF_X1LN  95158272ULL   // tiled bf16x2, K=128
#define OFF_YIN   103088128ULL  // packed bf16x2 [p][512]
#define OFF_YG    166526976ULL  // packed bf16x2 [p][256]
#define OFF_WB    198246400ULL
#define TOT_U     198369280ULL

__device__ unsigned g_u[TOT_U];

// ---------------------------------------------------------------------------
// helpers
// ---------------------------------------------------------------------------
__device__ __forceinline__ unsigned pk(float lo, float hi) {
    unsigned r;
    asm("cvt.rn.bf16x2.f32 %0, %1, %2;" : "=r"(r) : "f"(hi), "f"(lo));
    return r;
}
__device__ __forceinline__ float2 bf2f(unsigned u) {
    __nv_bfloat162 h = *reinterpret_cast<__nv_bfloat162*>(&u);
    return __bfloat1622float2(h);
}
__device__ __forceinline__ void mma16(float* d, const unsigned* a, const unsigned* b) {
    asm volatile(
        "mma.sync.aligned.m16n8k16.row.col.f32.bf16.bf16.f32 "
        "{%0,%1,%2,%3},{%4,%5,%6,%7},{%8,%9},{%0,%1,%2,%3};"
        : "+f"(d[0]), "+f"(d[1]), "+f"(d[2]), "+f"(d[3])
        : "r"(a[0]), "r"(a[1]), "r"(a[2]), "r"(a[3]), "r"(b[0]), "r"(b[1]));
}
__device__ __forceinline__ void ldsm4(unsigned& r0, unsigned& r1, unsigned& r2, unsigned& r3, unsigned a) {
    asm volatile("ldmatrix.sync.aligned.m8n8.x4.shared.b16 {%0,%1,%2,%3}, [%4];"
        : "=r"(r0), "=r"(r1), "=r"(r2), "=r"(r3) : "r"(a));
}
__device__ __forceinline__ void cpa16(unsigned d, const void* s) {
    asm volatile("cp.async.cg.shared.global [%0], [%1], 16;" :: "r"(d), "l"(s));
}
__device__ __forceinline__ void stg_cs(unsigned* p, unsigned v) {
    asm volatile("st.global.cs.u32 [%0], %1;" :: "l"(p), "r"(v));
}
__device__ __forceinline__ void stg_cs_f(float* p, float v) {
    asm volatile("st.global.cs.f32 [%0], %1;" :: "l"(p), "f"(v));
}
#define CP_COMMIT() asm volatile("cp.async.commit_group;" ::: "memory")
#define CP_WAIT2()  asm volatile("cp.async.wait_group 2;" ::: "memory")
#define CP_WAIT1()  asm volatile("cp.async.wait_group 1;" ::: "memory")
#define CP_WAIT0()  asm volatile("cp.async.wait_group 0;" ::: "memory")

// packed f32x2 helpers (sm_100-family PTX, not arch-accelerated)
__device__ __forceinline__ unsigned long long u2f2(unsigned u) {
    unsigned lo = u << 16, hi = u & 0xFFFF0000u;
    unsigned long long r;
    asm("mov.b64 %0, {%1,%2};" : "=l"(r) : "r"(lo), "r"(hi));
    return r;
}
__device__ __forceinline__ unsigned long long pkf2(float lo, float hi) {
    unsigned long long r;
    asm("mov.b64 %0, {%1,%2};" : "=l"(r) : "f"(lo), "f"(hi));
    return r;
}
__device__ __forceinline__ unsigned long long ffma2(
    unsigned long long a, unsigned long long b, unsigned long long c) {
    unsigned long long d;
    asm("fma.rn.f32x2 %0, %1, %2, %3;" : "=l"(d) : "l"(a), "l"(b), "l"(c));
    return d;
}
__device__ __forceinline__ void unf2(unsigned long long v, float& lo, float& hi) {
    asm("mov.b64 {%0,%1}, %2;" : "=f"(lo), "=f"(hi) : "l"(v));
}

// ---------------------------------------------------------------------------
// K0: weight prep -> packed bf16x2 in GEMM-tiled layout.
// WB: WqP[8192] | WKVP[16384] | WinP[65536] | WoutP[32768]
// ---------------------------------------------------------------------------
__global__ void k_wprep(const float* __restrict__ Wq, const float* __restrict__ Wk,
                        const float* __restrict__ Wv, const float* __restrict__ win,
                        const float* __restrict__ wout)
{
    int idx = blockIdx.x * 256 + threadIdx.x;
    if (idx >= 122880) return;
    unsigned* WB = g_u + OFF_WB;
    if (idx < 8192) {
        int n = idx >> 6, kp = idx & 63;
        WB[(kp >> 3) * 1024 + n * 8 + (kp & 7)] = pk(Wq[n * 128 + 2 * kp], Wq[n * 128 + 2 * kp + 1]);
    } else if (idx < 24576) {
        int j = idx - 8192; int n2 = j >> 6, kp = j & 63;
        const float* W = (n2 < 128) ? Wk : Wv;
        int n = n2 & 127;
        WB[8192 + (n2 >> 7) * 8192 + (kp >> 3) * 1024 + n * 8 + (kp & 7)]
            = pk(W[n * 128 + 2 * kp], W[n * 128 + 2 * kp + 1]);
    } else if (idx < 90112) {
        int j = idx - 24576; int n = j >> 6, kp = j & 63;
        WB[24576 + (n >> 7) * 8192 + (kp >> 3) * 1024 + (n & 127) * 8 + (kp & 7)]
            = pk(win[n * 128 + 2 * kp], win[n * 128 + 2 * kp + 1]);
    } else {
        int j = idx - 90112; int n = j >> 8, kp = j & 255;
        WB[90112 + (kp >> 3) * 1024 + n * 8 + (kp & 7)]
            = pk(wout[n * 512 + 2 * kp], wout[n * 512 + 2 * kp + 1]);
    }
}

// ---------------------------------------------------------------------------
// K1: LN1(x), bilinear mask/edge upsample -> tiled Aq / Akv (uint4 stores).
// x loads vectorized to float4.
// ---------------------------------------------------------------------------
__global__ void __launch_bounds__(256) k_prep(
    const float* __restrict__ x, const float* __restrict__ mask,
    const float* __restrict__ edge, const float* __restrict__ ln1w,
    const float* __restrict__ ln1b)
{
    __shared__ float xs[128 * 33];
    __shared__ float red[264], red2[264];
    __shared__ float ms[32], mu_s[32], rs_s[32];
    __shared__ int   cy0[32], cy1[32], cx0[32], cx1[32];
    __shared__ float cwy[32], cwx[32];
    __shared__ float w1s[128], b1s[128];

    int p0 = blockIdx.x * 32;
    int b = p0 / HW, hw0 = p0 % HW;
    const float* xb = x + (size_t)b * PB;
    if (threadIdx.x < 128) { w1s[threadIdx.x] = ln1w[threadIdx.x]; b1s[threadIdx.x] = ln1b[threadIdx.x]; }

    for (int e = threadIdx.x; e < 1024; e += 256) {
        int c = e >> 3, px = (e & 7) * 4;
        float4 v = *(const float4*)(xb + (size_t)c * HW + hw0 + px);
        float* d = xs + c * 33 + px;
        d[0] = v.x; d[1] = v.y; d[2] = v.z; d[3] = v.w;
    }
    if (threadIdx.x < 32) {
        int px = threadIdx.x;
        int hw = hw0 + px;
        int h2 = hw / 176, w2 = hw % 176;
        float fy = 0.25f * h2 - 0.375f; int iy = (int)floorf(fy); float ty = fy - iy;
        float fx = 0.25f * w2 - 0.375f; int ix = (int)floorf(fx); float tx = fx - ix;
        int y0 = iy < 0 ? 0 : iy, y1 = (iy + 1 > 43) ? 43 : iy + 1;
        int x0 = ix < 0 ? 0 : ix, x1 = (ix + 1 > 43) ? 43 : ix + 1;
        cy0[px] = y0; cy1[px] = y1; cx0[px] = x0; cx1[px] = x1;
        cwy[px] = ty; cwx[px] = tx;
        const float* mb = mask + b * NWIN;
        ms[px] = (1.f - ty) * ((1.f - tx) * mb[y0 * 44 + x0] + tx * mb[y0 * 44 + x1])
               +        ty  * ((1.f - tx) * mb[y1 * 44 + x0] + tx * mb[y1 * 44 + x1]);
    }
    __syncthreads();
    {
        int px = threadIdx.x & 31, j = threadIdx.x >> 5;
        float s = 0.f, s2 = 0.f;
        #pragma unroll
        for (int i = 0; i < 16; i++) {
            float v = xs[(j * 16 + i) * 33 + px];
            s += v; s2 += v * v;
        }
        red[j * 33 + px] = s; red2[j * 33 + px] = s2;
    }
    __syncthreads();
    if (threadIdx.x < 32) {
        int px = threadIdx.x; float s = 0.f, s2 = 0.f;
        #pragma unroll
        for (int j = 0; j < 8; j++) { s += red[j * 33 + px]; s2 += red2[j * 33 + px]; }
        float mu = s * (1.f / 128.f);
        float var = s2 * (1.f / 128.f) - mu * mu;
        mu_s[px] = mu; rs_s[px] = rsqrtf(var + 1e-5f);
    }
    __syncthreads();

    int px = threadIdx.x & 31, j = threadIdx.x >> 5;   // j = stage 0..7
    int p = p0 + px;
    size_t tbase = (size_t)(p >> 7) * 8192 + (size_t)j * 1024 + (size_t)(p & 127) * 8;
    {
        float mu = mu_s[px], rs = rs_s[px], m = ms[px];
        unsigned q[8];
        #pragma unroll
        for (int ii = 0; ii < 8; ii++) {
            int c = j * 16 + 2 * ii;
            float v0 = ((xs[c * 33 + px] - mu) * rs * w1s[c] + b1s[c]) * m;
            float v1 = ((xs[(c + 1) * 33 + px] - mu) * rs * w1s[c + 1] + b1s[c + 1]) * m;
            q[ii] = pk(v0, v1);
        }
        uint4* dst = (uint4*)(g_u + OFF_AKV + tbase);
        dst[0] = make_uint4(q[0], q[1], q[2], q[3]);
        dst[1] = make_uint4(q[4], q[5], q[6], q[7]);
    }
    __syncthreads();
    for (int e = threadIdx.x; e < 4096; e += 256) {
        int c = e >> 5, px2 = e & 31;
        const float* eb = edge + ((size_t)b * 128 + c) * NWIN;
        float ty = cwy[px2], tx = cwx[px2];
        float v = (1.f - ty) * ((1.f - tx) * eb[cy0[px2] * 44 + cx0[px2]] + tx * eb[cy0[px2] * 44 + cx1[px2]])
                +        ty  * ((1.f - tx) * eb[cy1[px2] * 44 + cx0[px2]] + tx * eb[cy1[px2] * 44 + cx1[px2]]);
        xs[c * 33 + px2] = v;
    }
    __syncthreads();
    {
        unsigned q[8];
        #pragma unroll
        for (int ii = 0; ii < 8; ii++) {
            int c = j * 16 + 2 * ii;
            q[ii] = pk(xs[c * 33 + px], xs[(c + 1) * 33 + px]);
        }
        uint4* dst = (uint4*)(g_u + OFF_AQ + tbase);
        dst[0] = make_uint4(q[0], q[1], q[2], q[3]);
        dst[1] = make_uint4(q[4], q[5], q[6], q[7]);
    }
}

// ---------------------------------------------------------------------------
// Shared GEMM mainloop pieces (R10-proven: 4-buffer, 3 in flight, 1 bar/stage)
// ---------------------------------------------------------------------------
#define GEMM_PREAMBLE() \
    int tid = threadIdx.x, lane = tid & 31, warp = tid >> 5; \
    int wm = warp >> 2, wn = warp & 3, t = lane & 3, g = lane >> 2; \
    unsigned smb = (unsigned)__cvta_generic_to_shared(sm); \
    int m_ = tid >> 1, q_ = tid & 1; \
    unsigned dA = smb + (unsigned)(2 * m_ + (q_ ^ ((m_ >> 2) & 1))) * 16; \
    unsigned dB = dA + 4096; \
    int itemA = wm * 64 + (lane & 15); \
    int khA = lane >> 4; \
    unsigned aAddr = smb + (unsigned)(2 * itemA + (khA ^ ((itemA >> 2) & 1))) * 16; \
    int itemB = wn * 32 + lane; \
    int bbit = (itemB >> 2) & 1; \
    unsigned bAddr0 = smb + 4096u + (unsigned)(2 * itemB + bbit) * 16; \
    unsigned bAddr1 = smb + 4096u + (unsigned)(2 * itemB + (1 ^ bbit)) * 16; \
    float acc[4][4][4]; \
    _Pragma("unroll") \
    for (int i = 0; i < 4; i++) \
        _Pragma("unroll") \
        for (int j = 0; j < 4; j++) \
            _Pragma("unroll") \
            for (int k = 0; k < 4; k++) acc[i][j][k] = 0.f;

#define GEMM_STAGE_BODY() \
    unsigned buf = (unsigned)(s & 3) * 8192u; \
    unsigned af[4][4], bf[4][2]; \
    ldsm4(bf[0][0], bf[1][0], bf[2][0], bf[3][0], bAddr0 + buf); \
    ldsm4(bf[0][1], bf[1][1], bf[2][1], bf[3][1], bAddr1 + buf); \
    _Pragma("unroll") \
    for (int tm = 0; tm < 4; tm++) \
        ldsm4(af[tm][0], af[tm][1], af[tm][2], af[tm][3], aAddr + buf + tm * 512u); \
    _Pragma("unroll") \
    for (int tm = 0; tm < 4; tm++) \
        _Pragma("unroll") \
        for (int tn = 0; tn < 4; tn++) \
            mma16(acc[tm][tn], af[tm], bf[tn]);

// ---------------------------------------------------------------------------
// K2a: fused Q/K/V GEMM. grid (PTOT/128, 3). y=0->Q, y=1->K half, y=2->V half.
// ---------------------------------------------------------------------------
__global__ void __launch_bounds__(256, 2) k_mma_qkv()
{
    __shared__ unsigned sm[4 * 2048];
    GEMM_PREAMBLE();
    int y = blockIdx.y;
    const unsigned* Ab = g_u + (y == 0 ? OFF_AQ : OFF_AKV)
                       + (size_t)blockIdx.x * 8192 + tid * 4;
    const unsigned* Bb = g_u + OFF_WB + (size_t)y * 8192 + tid * 4;

    #pragma unroll
    for (int s = 0; s < 3; s++) {
        unsigned off = s * 8192u;
        cpa16(dA + off, Ab + s * 1024);
        cpa16(dB + off, Bb + s * 1024);
        CP_COMMIT();
    }
    for (int s = 0; s < 8; s++) {
        if (s + 3 <= 8) CP_WAIT2();
        else if (s + 2 == 8) CP_WAIT1();
        else CP_WAIT0();
        __syncthreads();
        GEMM_STAGE_BODY();
        if (s + 3 < 8) {
            unsigned off = (unsigned)((s + 3) & 3) * 8192u;
            cpa16(dA + off, Ab + (s + 3) * 1024);
            cpa16(dB + off, Bb + (s + 3) * 1024);
        }
        CP_COMMIT();
    }

    int m0 = blockIdx.x * 128;
    unsigned* Cu = g_u + (y == 0 ? OFF_Q : OFF_KV);
    int np = (y == 0) ? 64 : 128;
    int nc0 = (y == 0) ? 0 : (y - 1) * 64;
    #pragma unroll
    for (int tm = 0; tm < 4; tm++)
        #pragma unroll
        for (int tn = 0; tn < 4; tn++) {
            int m = m0 + wm * 64 + tm * 16 + g;
            int n = wn * 32 + tn * 8 + 2 * t;
            Cu[(size_t)m * np + nc0 + (n >> 1)] = pk(acc[tm][tn][0], acc[tm][tn][1]);
            Cu[(size_t)(m + 8) * np + nc0 + (n >> 1)] = pk(acc[tm][tn][2], acc[tm][tn][3]);
        }
}

// ---------------------------------------------------------------------------
// K2b: generic GEMM (conv_in EPI=1/CS, conv_out EPI=2) — R10-proven.
// ---------------------------------------------------------------------------
template<int NSTAGE, int ASRC, int EPI, int CS>
__global__ void __launch_bounds__(256, 2) k_mma_t(
    const unsigned* __restrict__ At, const unsigned* __restrict__ Bt,
    unsigned* __restrict__ Cu, int Nd, float* __restrict__ outp)
{
    __shared__ unsigned sm[4 * 2048];
    GEMM_PREAMBLE();
    const unsigned* Ab;
    if (ASRC == 0) Ab = At + (size_t)blockIdx.x * (NSTAGE * 1024) + tid * 4;
    else           Ab = At + ((size_t)blockIdx.x * 128 + (tid >> 1)) * 256 + (tid & 1) * 4;
    const unsigned* Bb = Bt + (size_t)blockIdx.y * (NSTAGE * 1024) + tid * 4;

    #pragma unroll
    for (int s = 0; s < 3; s++) {
        if (s < NSTAGE) {
            unsigned off = s * 8192u;
            cpa16(dA + off, Ab + (ASRC == 0 ? s * 1024 : s * 8));
            cpa16(dB + off, Bb + s * 1024);
        }
        CP_COMMIT();
    }
    for (int s = 0; s < NSTAGE; s++) {
        if (s + 3 <= NSTAGE) CP_WAIT2();
        else if (s + 2 == NSTAGE) CP_WAIT1();
        else CP_WAIT0();
        __syncthreads();
        GEMM_STAGE_BODY();
        if (s + 3 < NSTAGE) {
            unsigned off = (unsigned)((s + 3) & 3) * 8192u;
            cpa16(dA + off, Ab + (ASRC == 0 ? (s + 3) * 1024 : (s + 3) * 8));
            cpa16(dB + off, Bb + (s + 3) * 1024);
        }
        CP_COMMIT();
    }

    int m0 = blockIdx.x * 128, n0 = blockIdx.y * 128;
    if (EPI == 1) {
        int np = Nd >> 1;
        #pragma unroll
        for (int tm = 0; tm < 4; tm++)
            #pragma unroll
            for (int tn = 0; tn < 4; tn++) {
                int m = m0 + wm * 64 + tm * 16 + g;
                int n = n0 + wn * 32 + tn * 8 + 2 * t;
                unsigned v0 = pk(acc[tm][tn][0], acc[tm][tn][1]);
                unsigned v1 = pk(acc[tm][tn][2], acc[tm][tn][3]);
                if (CS) {
                    stg_cs(Cu + (size_t)m * np + (n >> 1), v0);
                    stg_cs(Cu + (size_t)(m + 8) * np + (n >> 1), v1);
                } else {
                    Cu[(size_t)m * np + (n >> 1)] = v0;
                    Cu[(size_t)(m + 8) * np + (n >> 1)] = v1;
                }
            }
    } else {
        const float* x1 = (const float*)(g_u + OFF_X1);
        int b = m0 / HW, hw0 = m0 % HW;
        #pragma unroll
        for (int tm = 0; tm < 4; tm++)
            #pragma unroll
            for (int tn = 0; tn < 4; tn++) {
                int mrow = wm * 64 + tm * 16 + g;
                int n = wn * 32 + tn * 8 + 2 * t;
                size_t a0 = ((size_t)b * 128 + n) * HW + hw0 + mrow;
                stg_cs_f(outp + a0,          x1[a0] + acc[tm][tn][0]);
                stg_cs_f(outp + a0 + HW,     x1[a0 + HW] + acc[tm][tn][1]);
                stg_cs_f(outp + a0 + 8,      x1[a0 + 8] + acc[tm][tn][2]);
                stg_cs_f(outp + a0 + HW + 8, x1[a0 + HW + 8] + acc[tm][tn][3]);
            }
    }
}

// ---------------------------------------------------------------------------
// K3: channel attention + fused residual (R13 core), float4 epilogue.
// ds stored TRANSPOSED with stride 17: ds[kk*17 + j].
// ---------------------------------------------------------------------------
__global__ void __launch_bounds__(256) k_attn(const float* __restrict__ x)
{
    __shared__ float outs[32 * 129];
    __shared__ float buf[8 * 656];
    int bid = blockIdx.x;
    int chunk = bid % 61;
    int n = (bid / 61) % 16;
    int b = bid / (61 * 16);
    int ihw0 = chunk * 32;
    const unsigned* Qp  = g_u + OFF_Q;
    const unsigned* KVp = g_u + OFF_KV;
    float* x1 = (float*)(g_u + OFF_X1);
    int warp = threadIdx.x >> 5, lane = threadIdx.x & 31;
    float* qs = buf + warp * 656;
    float* ks = qs + 128;
    float* vs = qs + 256;
    float* ds = qs + 384;          // 16x16 stored transposed, stride 17
    int kk = lane & 15, hh = lane >> 4;

    for (int it = 0; it < 4; it++) {
        int g = it * 8 + warp;
        int ihw = ihw0 + g;
        if (ihw < NWIN) {
            int ih = ihw / 44, iw = ihw % 44;
            int h2 = ih * 4 + (n >> 2), w2 = iw * 4 + (n & 3);
            size_t p = (size_t)b * HW + (size_t)h2 * 176 + w2;
            {
                *(float2*)(qs + 2 * lane)      = bf2f(Qp[p * 64 + lane]);
                *(float2*)(qs + 64 + 2 * lane) = bf2f(Qp[p * 64 + 32 + lane]);
                *(float2*)(ks + 2 * lane)      = bf2f(KVp[p * 128 + lane]);
                *(float2*)(ks + 64 + 2 * lane) = bf2f(KVp[p * 128 + 32 + lane]);
                *(float2*)(vs + 2 * lane)      = bf2f(KVp[p * 128 + 64 + lane]);
                *(float2*)(vs + 64 + 2 * lane) = bf2f(KVp[p * 128 + 96 + lane]);
            }
            __syncwarp();
            {
                float kreg[8];
                #pragma unroll
                for (int i = 0; i < 8; i++) kreg[i] = ks[i * 16 + kk];
                #pragma unroll
                for (int t2 = 0; t2 < 8; t2++) {
                    int j = hh + 2 * t2;
                    float s = 0.f;
                    #pragma unroll
                    for (int i = 0; i < 8; i++) s += qs[i * 16 + j] * kreg[i];
                    ds[kk * 17 + j] = s * 0.25f;
                }
            }
            __syncwarp();
            if (lane < 16) {
                float mx = -1e30f;
                #pragma unroll
                for (int k2 = 0; k2 < 16; k2++) mx = fmaxf(mx, ds[k2 * 17 + lane]);
                float sm = 0.f;
                #pragma unroll
                for (int k2 = 0; k2 < 16; k2++) {
                    float ev = __expf(ds[k2 * 17 + lane] - mx);
                    ds[k2 * 17 + lane] = ev; sm += ev;
                }
                float inv = 1.f / sm;
                #pragma unroll
                for (int k2 = 0; k2 < 16; k2++) ds[k2 * 17 + lane] *= inv;
            }
            __syncwarp();
            {
                float dreg[16];
                #pragma unroll
                for (int k2 = 0; k2 < 16; k2++) dreg[k2] = ds[k2 * 17 + kk];
                #pragma unroll
                for (int t2 = 0; t2 < 4; t2++) {
                    int i = hh + 2 * t2;
                    float s = 0.f;
                    #pragma unroll
                    for (int k2 = 0; k2 < 16; k2++) s += dreg[k2] * vs[i * 16 + k2];
                    outs[g * 129 + i * 16 + kk] = s;
                }
            }
        }
    }
    __syncthreads();
    size_t base = ((size_t)b * 2048 + (size_t)n * 128) * 1936 + ihw0;
    if (chunk < 60) {
        // float4 path: 4 window-positions per access (1936 % 4 == 0 alignment ok)
        for (int e = threadIdx.x; e < 1024; e += 256) {
            int ch = e >> 3, gq = (e & 7) * 4;
            size_t idx = base + (size_t)ch * 1936 + gq;
            float4 xv = *(const float4*)(x + idx);
            float4 o;
            o.x = xv.x + outs[(gq + 0) * 129 + ch];
            o.y = xv.y + outs[(gq + 1) * 129 + ch];
            o.z = xv.z + outs[(gq + 2) * 129 + ch];
            o.w = xv.w + outs[(gq + 3) * 129 + ch];
            *(float4*)(x1 + idx) = o;
        }
    } else {
        for (int e = threadIdx.x; e < 4096; e += 256) {
            int ch = e >> 5, g = e & 31;
            if (ihw0 + g < NWIN) {
                size_t idx = base + (size_t)ch * 1936 + g;
                x1[idx] = x[idx] + outs[g * 129 + ch];
            }
        }
    }
}

// ---------------------------------------------------------------------------
// K4: LN2 over x1 (read-only) -> tiled X1LN packed bf16 (uint4 stores).
// ---------------------------------------------------------------------------
__global__ void __launch_bounds__(256) k_merge2(
    const float* __restrict__ ln2w, const float* __restrict__ ln2b)
{
    __shared__ float red[264], red2[264], mu_s[32], rs_s[32];
    __shared__ float w2s[128], b2s[128];
    int p0 = blockIdx.x * 32;
    int b = p0 / HW, hw0 = p0 % HW;
    int px = threadIdx.x & 31, j = threadIdx.x >> 5;
    if (threadIdx.x < 128) { w2s[threadIdx.x] = ln2w[threadIdx.x]; b2s[threadIdx.x] = ln2b[threadIdx.x]; }
    const float* x1 = (const float*)(g_u + OFF_X1);
    size_t base = (size_t)b * PB + hw0 + px;
    float v[16];
    float s = 0.f, s2 = 0.f;
    #pragma unroll
    for (int i = 0; i < 16; i++) {
        int c = j * 16 + i;
        float val = x1[base + (size_t)c * HW];
        v[i] = val; s += val; s2 += val * val;
    }
    red[j * 33 + px] = s; red2[j * 33 + px] = s2;
    __syncthreads();
    if (threadIdx.x < 32) {
        float ss = 0.f, ss2 = 0.f;
        #pragma unroll
        for (int j2 = 0; j2 < 8; j2++) { ss += red[j2 * 33 + threadIdx.x]; ss2 += red2[j2 * 33 + threadIdx.x]; }
        float mu = ss * (1.f / 128.f);
        float var = ss2 * (1.f / 128.f) - mu * mu;
        mu_s[threadIdx.x] = mu; rs_s[threadIdx.x] = rsqrtf(var + 1e-5f);
    }
    __syncthreads();
    float mu = mu_s[px], rs = rs_s[px];
    int p = p0 + px;
    unsigned qv[8];
    #pragma unroll
    for (int ii = 0; ii < 8; ii++) {
        int c = j * 16 + 2 * ii;
        float a = (v[2 * ii] - mu) * rs * w2s[c] + b2s[c];
        float bb = (v[2 * ii + 1] - mu) * rs * w2s[c + 1] + b2s[c + 1];
        qv[ii] = pk(a, bb);
    }
    uint4* dst = (uint4*)(g_u + OFF_X1LN + (size_t)(p >> 7) * 8192 + (size_t)j * 1024 + (size_t)(p & 127) * 8);
    dst[0] = make_uint4(qv[0], qv[1], qv[2], qv[3]);
    dst[1] = make_uint4(qv[4], qv[5], qv[6], qv[7]);
}

// ---------------------------------------------------------------------------
// K6: depthwise 3x3 + exact GELU gate, packed f32x2 accumulation.
// ---------------------------------------------------------------------------
__device__ __forceinline__ void dw_row6(
    const unsigned* __restrict__ yin, int b, int h, int w0, int cp,
    unsigned* U, unsigned* V)
{
    #pragma unroll
    for (int dw = 0; dw < 6; dw++) { U[dw] = 0u; V[dw] = 0u; }
    if (h < 0 || h >= 176) return;
    #pragma unroll
    for (int dw = 0; dw < 6; dw++) {
        int ww = w0 - 1 + dw;
        if (ww < 0 || ww >= 176) continue;
        size_t base = ((size_t)b * HW + (size_t)h * 176 + ww) * 512;
        U[dw] = yin[base + cp];
        V[dw] = yin[base + 256 + cp];
    }
}

__global__ void __launch_bounds__(256) k_dwconv(const float* __restrict__ wdw)
{
    int cp = threadIdx.x;
    int blk = blockIdx.x;
    int wg = blk % 44;
    int hs = (blk / 44) % 8;
    int b  = blk / (44 * 8);
    int w0 = wg * 4;
    int h0 = hs * 22;
    const unsigned* yin = g_u + OFF_YIN;
    unsigned* yg = g_u + OFF_YG;
    int c0 = 2 * cp;
    unsigned long long wpA[9], wpB[9];
    #pragma unroll
    for (int t = 0; t < 9; t++) {
        wpA[t] = pkf2(__ldg(&wdw[c0 * 9 + t]), __ldg(&wdw[(c0 + 1) * 9 + t]));
        wpB[t] = pkf2(__ldg(&wdw[(512 + c0) * 9 + t]), __ldg(&wdw[(513 + c0) * 9 + t]));
    }
    unsigned U[3][6], V[3][6];
    dw_row6(yin, b, h0 - 1, w0, cp, U[0], V[0]);
    dw_row6(yin, b, h0,     w0, cp, U[1], V[1]);
    dw_row6(yin, b, h0 + 1, w0, cp, U[2], V[2]);

    for (int h = h0; h < h0 + 22; h++) {
        unsigned long long accA[4], accB[4];
        #pragma unroll
        for (int o = 0; o < 4; o++) { accA[o] = 0ULL; accB[o] = 0ULL; }
        #pragma unroll
        for (int dw = 0; dw < 6; dw++) {
            #pragma unroll
            for (int rr = 0; rr < 3; rr++) {
                unsigned long long ua = u2f2(U[rr][dw]);
                unsigned long long vb = u2f2(V[rr][dw]);
                #pragma unroll
                for (int o = 0; o < 4; o++) {
                    int cc = dw - o;
                    if (cc >= 0 && cc < 3) {
                        int tt = rr * 3 + cc;
                        accA[o] = ffma2(ua, wpA[tt], accA[o]);
                        accB[o] = ffma2(vb, wpB[tt], accB[o]);
                    }
                }
            }
        }
        #pragma unroll
        for (int o = 0; o < 4; o++) {
            float a0, a1, g0, g1;
            unf2(accA[o], a0, a1);
            unf2(accB[o], g0, g1);
            float e0 = 0.5f * a0 * (1.f + erff(a0 * 0.70710678118654752f));
            float e1 = 0.5f * a1 * (1.f + erff(a1 * 0.70710678118654752f));
            int p = b * HW + h * 176 + w0 + o;
            stg_cs(yg + (size_t)p * 256 + cp, pk(e0 * g0, e1 * g1));
        }
        #pragma unroll
        for (int dw = 0; dw < 6; dw++) {
            U[0][dw] = U[1][dw]; U[1][dw] = U[2][dw];
            V[0][dw] = V[1][dw]; V[1][dw] = V[2][dw];
        }
        dw_row6(yin, b, h + 2, w0, cp, U[2], V[2]);
    }
}

// ---------------------------------------------------------------------------
extern "C" void kernel_launch(void* const* d_in, const int* in_sizes, int n_in,
                              void* d_out, int out_size)
{
    const float* x    = (const float*)d_in[0];
    const float* mask = (const float*)d_in[1];
    const float* edge = (const float*)d_in[2];
    const float* ln1w = (const float*)d_in[3];
    const float* ln1b = (const float*)d_in[4];
    const float* Wq   = (const float*)d_in[5];
    const float* Wk   = (const float*)d_in[6];
    const float* Wv   = (const float*)d_in[7];
    const float* ln2w = (const float*)d_in[8];
    const float* ln2b = (const float*)d_in[9];
    const float* w_in = (const float*)d_in[10];
    const float* w_dw = (const float*)d_in[11];
    const float* w_out= (const float*)d_in[12];
    float* outp = (float*)d_out;

    unsigned* G = nullptr;
    cudaGetSymbolAddress((void**)&G, g_u);

    // K0: weights -> tiled packed bf16x2
    k_wprep<<<(122880 + 255) / 256, 256>>>(Wq, Wk, Wv, w_in, w_out);

    // K1: LN1 + resize -> tiled Aq/Akv
    k_prep<<<PTOT / 32, 256>>>(x, mask, edge, ln1w, ln1b);

    // K2a: fused Q/K/V GEMM (one launch, grid.y = 3)
    k_mma_qkv<<<dim3(PTOT / 128, 3), 256>>>();

    // K3: channel attention + fused residual -> x1 (fp32 NCHW)
    k_attn<<<4 * 16 * 61, 256>>>(x);

    // K4: LN2(x1) -> tiled X1LN
    k_merge2<<<PTOT / 32, 256>>>(ln2w, ln2b);

    // K5: conv1x1 128->1024 -> y_in packed bf16 (evict-first C stores)
    k_mma_t<8, 0, 1, 1><<<dim3(PTOT / 128, 8), 256>>>(G + OFF_X1LN, G + OFF_WB + 24576, G + OFF_YIN, 1024, nullptr);

    // K6: depthwise 3x3 + GELU gate -> y_g packed rows (f32x2 math, cs stores)
    k_dwconv<<<BATCH * 44 * 8, 256>>>(w_dw);

    // K7: conv1x1 512->128 + residual -> d_out (NCHW, cs stores)
    k_mma_t<32, 1, 2, 0><<<dim3(PTOT / 128, 1), 256>>>(G + OFF_YG, G + OFF_WB + 90112, nullptr, 128, outp);
}